// round 12
// baseline (speedup 1.0000x reference)
#include <cuda_runtime.h>

// TempoStateRNNCell: c_t = a_t * c_{t-1} + b_t along time (T=2048).
// inputs: (16, 2048, 4096) fp32, [:, :, :2048]=a, [:, :, 2048:]=b
// output: (16, 2048, 2048) fp32. Traffic floor 768 MB -> HBM-bound.
//
// R12: same 6-stage x 16-step SMEM ring (96 KB/CTA, 256 CTAs x 128 thr),
// but loads now go through cp.async.bulk (UBLKCP) issued by one thread
// per CTA, completing on an mbarrier (complete_tx). Block-sized requests
// from the async engine + zero per-thread load-issue overhead.

#define UNITS 2048
#define T_LEN 2048
#define BATCH 16
#define ROW   (2 * UNITS)            // 4096 floats per (batch, t) input row
#define BLK   128                    // threads = units per CTA
#define STEPS 16                     // timesteps per stage
#define NST   6                      // ring stages
#define STAGE_FLOATS (STEPS * BLK)   // 2048 floats (8 KB) per matrix per stage
#define RING_BYTES (2 * NST * STAGE_FLOATS * 4)       // 96 KB
#define SMEM_BYTES (RING_BYTES + NST * 8)             // + mbarriers
#define NSTG  (T_LEN / STEPS)        // 128 stages
#define STAGE_BYTES (2 * STAGE_FLOATS * 4)            // 16 KB per stage

__device__ __forceinline__ unsigned s2u(const void* p) {
    return (unsigned)__cvta_generic_to_shared(p);
}

__device__ __forceinline__ void mbar_init(unsigned mbar, unsigned count) {
    asm volatile("mbarrier.init.shared.b64 [%0], %1;" :: "r"(mbar), "r"(count) : "memory");
}
__device__ __forceinline__ void mbar_expect_tx(unsigned mbar, unsigned bytes) {
    asm volatile("mbarrier.arrive.expect_tx.shared.b64 _, [%0], %1;"
                 :: "r"(mbar), "r"(bytes) : "memory");
}
__device__ __forceinline__ void bulk_g2s(unsigned sdst, const void* gsrc,
                                         unsigned bytes, unsigned mbar) {
    asm volatile("cp.async.bulk.shared::cta.global.mbarrier::complete_tx::bytes "
                 "[%0], [%1], %2, [%3];"
                 :: "r"(sdst), "l"(gsrc), "r"(bytes), "r"(mbar) : "memory");
}
__device__ __forceinline__ void mbar_wait(unsigned mbar, unsigned parity) {
    unsigned done;
    asm volatile(
        "{\n\t.reg .pred p;\n\t"
        "mbarrier.try_wait.parity.acquire.cta.shared::cta.b64 p, [%1], %2;\n\t"
        "selp.b32 %0, 1, 0, p;\n\t}"
        : "=r"(done) : "r"(mbar), "r"(parity) : "memory");
    if (!done) {
        asm volatile(
            "{\n\t.reg .pred P1;\n\t"
            "WAIT_LOOP_%=:\n\t"
            "mbarrier.try_wait.parity.acquire.cta.shared::cta.b64 P1, [%0], %1, 0x989680;\n\t"
            "@P1 bra.uni WAIT_DONE_%=;\n\t"
            "bra.uni WAIT_LOOP_%=;\n\t"
            "WAIT_DONE_%=:\n\t}"
            :: "r"(mbar), "r"(parity) : "memory");
    }
}

__global__ void __launch_bounds__(BLK)
tempo_scan_kernel(const float* __restrict__ in, float* __restrict__ out)
{
    extern __shared__ __align__(1024) float smem[];
    float* sa = smem;                        // [NST][STEPS][BLK]
    float* sb = smem + NST * STAGE_FLOATS;   // [NST][STEPS][BLK]
    const unsigned mbar0 = s2u(smem) + RING_BYTES;   // NST x 8B mbarriers

    const int tid   = threadIdx.x;
    const int batch = blockIdx.x >> 4;
    const int unit0 = (blockIdx.x & 15) * BLK;

    const float* __restrict__ gin = in + (size_t)batch * T_LEN * ROW + unit0;
    float* __restrict__ gout = out + (size_t)batch * T_LEN * UNITS + unit0 + tid;

    if (tid == 0) {
        #pragma unroll
        for (int k = 0; k < NST; ++k) mbar_init(mbar0 + 8 * k, 1);
        asm volatile("fence.proxy.async.shared::cta;" ::: "memory");
    }
    __syncthreads();

    // Single-thread stage issue: 16 KB via 32 bulk copies of 512 B.
    auto issue = [&](int s) {
        if (s < NSTG) {
            const int slot = s % NST;
            const unsigned mb = mbar0 + 8 * slot;
            const size_t tb = (size_t)s * STEPS;
            const unsigned da = s2u(sa + slot * STAGE_FLOATS);
            const unsigned db = s2u(sb + slot * STAGE_FLOATS);
            mbar_expect_tx(mb, STAGE_BYTES);
            #pragma unroll
            for (int r = 0; r < STEPS; ++r) {
                const float* g = gin + (tb + r) * ROW;
                bulk_g2s(da + r * BLK * 4, g,         BLK * 4, mb);
                bulk_g2s(db + r * BLK * 4, g + UNITS, BLK * 4, mb);
            }
        }
    };

    if (tid == 0)
        for (int s = 0; s < NST - 1; ++s) issue(s);

    float c = 0.0f;   // c_0 = fma(a_0, 0, b_0) = b_0

    for (int s = 0; s < NSTG; ++s) {
        // Refill slot (s-1)%NST: its readers all passed iteration s-1's
        // trailing __syncthreads, so tid 0 is ordered after them here.
        if (tid == 0) issue(s + NST - 1);

        const int slot = s % NST;
        mbar_wait(mbar0 + 8 * slot, (s / NST) & 1);   // acquire: data visible

        const float* da = sa + slot * STAGE_FLOATS + tid;
        const float* db = sb + slot * STAGE_FLOATS + tid;

        float ar[STEPS], br[STEPS];
        #pragma unroll
        for (int i = 0; i < STEPS; ++i) {
            ar[i] = da[i * BLK];
            br[i] = db[i * BLK];
        }

        const size_t tb = (size_t)s * STEPS;
        #pragma unroll
        for (int i = 0; i < STEPS; ++i) {
            c = fmaf(ar[i], c, br[i]);
            __stcs(gout + (tb + i) * UNITS, c);
        }

        __syncthreads();   // all reads of slot s done before it is refilled
    }
}

extern "C" void kernel_launch(void* const* d_in, const int* in_sizes, int n_in,
                              void* d_out, int out_size)
{
    const float* in  = (const float*)d_in[0];
    float*       out = (float*)d_out;

    // Raise dynamic smem limit (attribute, not an allocation)
    cudaFuncSetAttribute(tempo_scan_kernel,
                         cudaFuncAttributeMaxDynamicSharedMemorySize, SMEM_BYTES);

    const int grid = BATCH * (UNITS / BLK);   // 256 CTAs
    tempo_scan_kernel<<<grid, BLK, SMEM_BYTES>>>(in, out);
}